// round 4
// baseline (speedup 1.0000x reference)
#include <cuda_runtime.h>
#include <math.h>

#define HH       256
#define NHEADS   8
#define MAX_N    1024
#define MAX_EDGES 600000
#define SUB      32

// ---------------- scratch (device globals; no allocation allowed) -------------
__device__ int    g_cnt2[MAX_N * SUB];
__device__ int    g_cur2[MAX_N * SUB];
__device__ int    g_roff[MAX_N + 1];
__device__ int    g_deg1[MAX_N];
__device__ int    g_deg2[MAX_N];
__device__ float  g_asum[MAX_N * 3];
__device__ float4 g_epack[MAX_EDGES];          // (src_as_float, a0, a1, a2)
__device__ float  g_h [MAX_N * HH];
__device__ float  g_xl[MAX_N * HH];
__device__ float  g_xr[MAX_N * HH];
__device__ float  g_A [MAX_N * HH];
__device__ float  g_B [MAX_N * HH];

// ---------------- f32x2 packed helpers (bit-exact fp32, 2x FFMA tput) ---------
__device__ __forceinline__ unsigned long long pk2(float a, float b) {
    unsigned long long r;
    asm("mov.b64 %0, {%1,%2};" : "=l"(r) : "f"(a), "f"(b));
    return r;
}
__device__ __forceinline__ void upk2(unsigned long long v, float& a, float& b) {
    asm("mov.b64 {%0,%1}, %2;" : "=f"(a), "=f"(b) : "l"(v));
}
__device__ __forceinline__ void fma2(unsigned long long& d, unsigned long long a,
                                     unsigned long long b) {
    asm("fma.rn.f32x2 %0, %1, %2, %0;" : "+l"(d) : "l"(a), "l"(b));
}

// ---------------- setup kernels ------------------------------------------------
__global__ void k_init(int N) {
    int t = blockIdx.x * blockDim.x + threadIdx.x;
    if (t < N) {
        g_deg1[t] = 0; g_deg2[t] = 0;
        g_asum[3 * t] = 0.f; g_asum[3 * t + 1] = 0.f; g_asum[3 * t + 2] = 0.f;
#pragma unroll
        for (int s = 0; s < SUB; s++) g_cnt2[t * SUB + s] = 0;
    }
}

__global__ void k_edge_stats(const int* __restrict__ ei, const float* __restrict__ ea,
                             int E) {
    int e = blockIdx.x * blockDim.x + threadIdx.x;
    if (e >= E) return;
    int s = ei[e], d = ei[E + e];
    float a0 = ea[3 * e], a1 = ea[3 * e + 1], a2 = ea[3 * e + 2];
    atomicAdd(&g_cnt2[d * SUB + (e & (SUB - 1))], 1);     // RED, no return
    atomicAdd(&g_asum[3 * d + 0], a0);
    atomicAdd(&g_asum[3 * d + 1], a1);
    atomicAdd(&g_asum[3 * d + 2], a2);
    // argmax with first-occurrence ties (matches jnp.argmax)
    int best = 0; float bv = a0;
    if (a1 > bv) { best = 1; bv = a1; }
    if (a2 > bv) { best = 2; }
    if (best == 1) { atomicAdd(&g_deg1[s], 1); atomicAdd(&g_deg1[d], 1); }
    else if (best == 2) { atomicAdd(&g_deg2[s], 1); atomicAdd(&g_deg2[d], 1); }
}

// prefix scan of segment lengths (cnt+1 for self-loop), sub-bucket bases,
// and self-loop packed entry
__global__ void k_scan(int N) {
    __shared__ int sc[1024];
    int t = threadIdx.x;
    int subc[SUB];
    int cnt = 0;
    if (t < N) {
#pragma unroll
        for (int s = 0; s < SUB; s++) { subc[s] = g_cnt2[t * SUB + s]; cnt += subc[s]; }
    }
    int len = (t < N) ? (cnt + 1) : 0;
    sc[t] = len;
    __syncthreads();
    for (int off = 1; off < 1024; off <<= 1) {
        int v = (t >= off) ? sc[t - off] : 0;
        __syncthreads();
        sc[t] += v;
        __syncthreads();
    }
    if (t < N) {
        int incl = sc[t];
        int excl = incl - len;
        g_roff[t + 1] = incl;
        if (t == 0) g_roff[0] = 0;
        int off = excl;
#pragma unroll
        for (int s = 0; s < SUB; s++) { g_cur2[t * SUB + s] = off; off += subc[s]; }
        int slot = excl + cnt;                     // self-loop at end of segment
        float c = fmaxf((float)cnt, 1.0f);
        g_epack[slot] = make_float4(__int_as_float(t),
                                    g_asum[3 * t + 0] / c,
                                    g_asum[3 * t + 1] / c,
                                    g_asum[3 * t + 2] / c);
    }
}

__global__ void k_scatter(const int* __restrict__ ei, const float* __restrict__ ea,
                          int E) {
    int e = blockIdx.x * blockDim.x + threadIdx.x;
    if (e >= E) return;
    int s = ei[e], d = ei[E + e];
    int pos = atomicAdd(&g_cur2[d * SUB + (e & (SUB - 1))], 1);
    g_epack[pos] = make_float4(__int_as_float(s), ea[3 * e], ea[3 * e + 1], ea[3 * e + 2]);
}

__global__ void k_emb(const float* __restrict__ x, const float* __restrict__ W,
                      const float* __restrict__ b) {
    int n = blockIdx.x, t = threadIdx.x;
    g_h[n * HH + t] = x[n] * W[t] + b[t];
}

// xl = h@Wl + bl ; xr = h@Wr + br
// block = 8 nodes x 128 channels (blockIdx.y = channel half) -> 128 blocks
__global__ void __launch_bounds__(128)
k_nodelin(const float* __restrict__ Wl, const float* __restrict__ bl,
          const float* __restrict__ Wr, const float* __restrict__ br,
          int l, int N) {
    __shared__ float hr[8][HH];
    int nb = blockIdx.x * 8;
    int ch = blockIdx.y * 128 + threadIdx.x;
    for (int idx = threadIdx.x; idx < 8 * HH; idx += 128) {
        int r = idx >> 8, c = idx & 255;
        int n = nb + r;
        hr[r][c] = (n < N) ? g_h[n * HH + c] : 0.f;
    }
    __syncthreads();
    const float* WL = Wl + (size_t)l * HH * HH;
    const float* WR = Wr + (size_t)l * HH * HH;
    float blv = bl[l * HH + ch], brv = br[l * HH + ch];
    float aL[8], aR[8];
#pragma unroll
    for (int r = 0; r < 8; r++) { aL[r] = blv; aR[r] = brv; }
#pragma unroll 4
    for (int c = 0; c < HH; c++) {
        float wl = WL[c * HH + ch], wr = WR[c * HH + ch];
#pragma unroll
        for (int r = 0; r < 8; r++) {
            aL[r] = fmaf(hr[r][c], wl, aL[r]);
            aR[r] = fmaf(hr[r][c], wr, aR[r]);
        }
    }
#pragma unroll
    for (int r = 0; r < 8; r++) {
        int n = nb + r;
        if (n < N) { g_xl[n * HH + ch] = aL[r]; g_xr[n * HH + ch] = aR[r]; }
    }
}

// one block (256 threads, 8 warps) per destination node. 1 warp = 1 edge across
// all 256 channels (lane owns 8 channels; head = 4 lanes). Edge descriptors read
// directly (warp-uniform broadcast) -> no smem staging / syncs in mainloop.
// No running max: scores are O(1), exp() safe -> edges fully independent.
__global__ void __launch_bounds__(256, 3)
k_gat(const float* __restrict__ We, const float* __restrict__ att,
      const float* __restrict__ gb, const float* __restrict__ lng,
      const float* __restrict__ lnb, int l) {
    __shared__ float sacc[8][HH];
    __shared__ float sden[8][NHEADS];
    __shared__ float red[8];
    int n = blockIdx.x, t = threadIdx.x;
    int w = t >> 5, lane = t & 31;
    int cb = 8 * lane;                 // channel base of this lane
    int head = lane >> 2;

    float xr8[8], w0[8], w1[8], w2[8], at8[8];
    const float* Wep = We + (size_t)(l * 3) * HH;
#pragma unroll
    for (int k = 0; k < 8; k++) {
        int c = cb + k;
        xr8[k] = g_xr[n * HH + c];
        w0[k] = Wep[c]; w1[k] = Wep[HH + c]; w2[k] = Wep[2 * HH + c];
        at8[k] = att[(l * NHEADS + head) * 32 + (c & 31)];
    }
    float acc[8];
#pragma unroll
    for (int k = 0; k < 8; k++) acc[k] = 0.f;
    float den = 0.f;

    int e0 = g_roff[n], e1 = g_roff[n + 1];
#pragma unroll 2
    for (int i = e0 + w; i < e1; i += 8) {
        float4 e = g_epack[i];                       // warp-uniform broadcast
        int s = __float_as_int(e.x);
        const float4* xp = (const float4*)(g_xl + (size_t)s * HH + cb);
        float4 xa = xp[0], xb = xp[1];
        float xv[8] = {xa.x, xa.y, xa.z, xa.w, xb.x, xb.y, xb.z, xb.w};
        float d = 0.f;
#pragma unroll
        for (int k = 0; k < 8; k++) {
            float sc = xv[k] + xr8[k];
            sc = fmaf(e.y, w0[k], sc);
            sc = fmaf(e.z, w1[k], sc);
            sc = fmaf(e.w, w2[k], sc);
            sc = fmaf(0.8f, fmaxf(sc, 0.f), 0.2f * sc);   // leaky_relu 0.2
            d = fmaf(sc, at8[k], d);
        }
        d += __shfl_xor_sync(0xffffffffu, d, 1);
        d += __shfl_xor_sync(0xffffffffu, d, 2);          // head-sum (4 lanes)
        float wgt = __expf(d);
        den += wgt;
#pragma unroll
        for (int k = 0; k < 8; k++) acc[k] = fmaf(wgt, xv[k], acc[k]);
    }
    *(float4*)&sacc[w][cb]     = make_float4(acc[0], acc[1], acc[2], acc[3]);
    *(float4*)&sacc[w][cb + 4] = make_float4(acc[4], acc[5], acc[6], acc[7]);
    if ((lane & 3) == 0) sden[w][head] = den;
    __syncthreads();

    // combine 8 warp-partials; 256 threads -> 1 channel each; then LayerNorm
    int ch = t;
    int hd = ch >> 5;
    float dsum = 0.f, a = 0.f;
#pragma unroll
    for (int k = 0; k < 8; k++) { dsum += sden[k][hd]; a += sacc[k][ch]; }
    float o = a / dsum + gb[l * HH + ch] + g_h[n * HH + ch];

    float v = o;
#pragma unroll
    for (int off = 16; off > 0; off >>= 1) v += __shfl_xor_sync(0xffffffffu, v, off);
    if (lane == 0) red[w] = v;
    __syncthreads();
    float mu = (red[0] + red[1] + red[2] + red[3] +
                red[4] + red[5] + red[6] + red[7]) * (1.0f / HH);
    float dv = o - mu;
    float q = dv * dv;
#pragma unroll
    for (int off = 16; off > 0; off >>= 1) q += __shfl_xor_sync(0xffffffffu, q, off);
    __syncthreads();
    if (lane == 0) red[w] = q;
    __syncthreads();
    float var = (red[0] + red[1] + red[2] + red[3] +
                 red[4] + red[5] + red[6] + red[7]) * (1.0f / HH);
    float rstd = rsqrtf(var + 1e-5f);
    float y = dv * rstd * lng[l * HH + ch] + lnb[l * HH + ch];
    g_h[n * HH + ch] = fmaxf(y, 0.f);
}

// graph pooling + value head + Potts energy
__global__ void k_graph(const float* __restrict__ v1W, const float* __restrict__ v1b,
                        const float* __restrict__ v2W, const float* __restrict__ v2b,
                        const float* __restrict__ coup, float* __restrict__ out,
                        int N, long long P) {
    __shared__ float gr[2 * HH];
    __shared__ float psum[2][HH];
    __shared__ float pmax[2][HH];
    __shared__ float sred[512];
    int t = threadIdx.x;
    int half = t >> 8, ch = t & 255;
    int nh = N >> 1;
    {
        float s = 0.f, mx = -1e30f;
        for (int n = half * nh; n < (half + 1) * nh; n++) {
            float v = g_h[n * HH + ch];
            s += v; mx = fmaxf(mx, v);
        }
        psum[half][ch] = s; pmax[half][ch] = mx;
    }
    __syncthreads();
    if (t < HH) {
        gr[t] = (psum[0][t] + psum[1][t]) / (float)N;
        gr[HH + t] = fmaxf(pmax[0][t], pmax[1][t]);
    }
    __syncthreads();
    float contrib = 0.f;
    if (t < HH) {
        float a = v1b[t];
        for (int c = 0; c < 2 * HH; c++) a = fmaf(gr[c], v1W[c * HH + t], a);
        a = fmaxf(a, 0.f);
        contrib = a * v2W[t];
    }
    sred[t] = contrib;
    __syncthreads();
    for (int off = 256; off > 0; off >>= 1) {
        if (t < off) sred[t] += sred[t + off];
        __syncthreads();
    }
    if (t == 0) out[P] = sred[0] + v2b[0];

    float e = 0.f;
    for (int n = t; n < N; n += 512) {
        float d1 = (float)g_deg1[n], d2 = (float)g_deg2[n];
        e += d1 * d1 + d2 * d2;
    }
    __syncthreads();
    sred[t] = e;
    __syncthreads();
    for (int off = 256; off > 0; off >>= 1) {
        if (t < off) sred[t] += sred[t + off];
        __syncthreads();
    }
    if (t == 0) out[P + 1] = coup[0] * sred[0] / (2.0f * (float)N);
}

// A = h @ p1_W[:H] + p1_b,  B = h @ p1_W[H:]   (factorized pair-MLP layer 1)
// block = 8 nodes x 128 channels -> 128 blocks
__global__ void __launch_bounds__(128)
k_AB(const float* __restrict__ p1W, const float* __restrict__ p1b, int N) {
    __shared__ float hr[8][HH];
    int nb = blockIdx.x * 8;
    int ch = blockIdx.y * 128 + threadIdx.x;
    for (int idx = threadIdx.x; idx < 8 * HH; idx += 128) {
        int r = idx >> 8, c = idx & 255;
        int n = nb + r;
        hr[r][c] = (n < N) ? g_h[n * HH + c] : 0.f;
    }
    __syncthreads();
    float a[8], b[8];
    float bv = p1b[ch];
#pragma unroll
    for (int r = 0; r < 8; r++) { a[r] = bv; b[r] = 0.f; }
#pragma unroll 4
    for (int c = 0; c < HH; c++) {
        float wt = p1W[c * HH + ch];
        float wb = p1W[(c + HH) * HH + ch];
#pragma unroll
        for (int r = 0; r < 8; r++) {
            a[r] = fmaf(hr[r][c], wt, a[r]);
            b[r] = fmaf(hr[r][c], wb, b[r]);
        }
    }
#pragma unroll
    for (int r = 0; r < 8; r++) {
        int n = nb + r;
        if (n < N) { g_A[n * HH + ch] = a[r]; g_B[n * HH + ch] = b[r]; }
    }
}

// fused all-pairs MLP: q = relu(A[i]+B[j]); out2 = relu(q@W2+b2); logit = out2.w3+b3
// block = 128 pairs x 128 outputs, K in chunks of 32; smem operands pre-packed
// as u64 so the inner loop is pure LDS.64 + fma.rn.f32x2.
#define PCHUNK 32
__global__ void __launch_bounds__(256, 2)
k_pairs(const float* __restrict__ p2W, const float* __restrict__ p2b,
        const float* __restrict__ p3W, const float* __restrict__ p3b,
        float* __restrict__ out, int N, long long P) {
    __shared__ unsigned long long qs2[128][PCHUNK];   // (q,q) duplicated
    __shared__ unsigned long long w2s[PCHUNK][64];    // packed weight pairs
    __shared__ int si[128], sj[128];
    int tid = threadIdx.x;
    int tx = tid & 15, ty = tid >> 4;
    long long pbase = (long long)blockIdx.x * 128;

    if (tid < 128) {
        long long p = pbase + tid;
        if (p > P - 1) p = P - 1;
        float tn = 2.0f * N - 1.0f;
        float disc = fmaxf(tn * tn - 8.0f * (float)p, 0.0f);
        int i = (int)((tn - sqrtf(disc)) * 0.5f);
        if (i < 0) i = 0;
        if (i > N - 2) i = N - 2;
        while ((long long)(i + 1) * (2 * N - 2 - i) / 2 <= p) i++;
        while ((long long)i * (2 * N - 1 - i) / 2 > p) i--;
        int j = i + 1 + (int)(p - (long long)i * (2 * N - 1 - i) / 2);
        si[tid] = i; sj[tid] = j;
    }

    unsigned long long acc[8][4] = {};
    for (int c0 = 0; c0 < HH; c0 += PCHUNK) {
        __syncthreads();
        for (int idx = tid; idx < 128 * PCHUNK; idx += 256) {
            int pr = idx >> 5, c = idx & 31;
            float q = g_A[si[pr] * HH + c0 + c] + g_B[sj[pr] * HH + c0 + c];
            q = q > 0.f ? q : 0.f;
            qs2[pr][c] = pk2(q, q);
        }
        for (int idx = tid; idx < PCHUNK * 64; idx += 256) {
            int c = idx >> 6, id = idx & 63;
            int k0 = (id & 15) + ((id >> 4) << 5);
            w2s[c][id] = pk2(p2W[(c0 + c) * 128 + k0],
                             p2W[(c0 + c) * 128 + k0 + 16]);
        }
        __syncthreads();
#pragma unroll 4
        for (int c = 0; c < PCHUNK; c++) {
            unsigned long long b2[4];
#pragma unroll
            for (int q = 0; q < 4; q++) b2[q] = w2s[c][tx + 16 * q];
#pragma unroll
            for (int r = 0; r < 8; r++) {
                unsigned long long a2 = qs2[ty + 16 * r][c];
#pragma unroll
                for (int q = 0; q < 4; q++) fma2(acc[r][q], a2, b2[q]);
            }
        }
    }

    float b3v = p3b[0];
#pragma unroll
    for (int r = 0; r < 8; r++) {
        float part = 0.f;
#pragma unroll
        for (int q = 0; q < 4; q++) {
            float v0, v1;
            upk2(acc[r][q], v0, v1);
            int k0 = tx + 32 * q, k1 = k0 + 16;
            v0 += p2b[k0]; v0 = fmaxf(v0, 0.f); part = fmaf(v0, p3W[k0], part);
            v1 += p2b[k1]; v1 = fmaxf(v1, 0.f); part = fmaf(v1, p3W[k1], part);
        }
#pragma unroll
        for (int o = 8; o > 0; o >>= 1)
            part += __shfl_xor_sync(0xffffffffu, part, o);
        if (tx == 0) {
            long long p = pbase + ty + 16 * r;
            if (p < P) out[p] = part + b3v;
        }
    }
}

// ---------------- launch ------------------------------------------------------
extern "C" void kernel_launch(void* const* d_in, const int* in_sizes, int n_in,
                              void* d_out, int out_size) {
    const float* x    = (const float*)d_in[0];
    const int*   ei   = (const int*)  d_in[1];
    const float* ea   = (const float*)d_in[2];
    const float* embW = (const float*)d_in[3];
    const float* embB = (const float*)d_in[4];
    const float* Wl   = (const float*)d_in[5];
    const float* bl   = (const float*)d_in[6];
    const float* Wr   = (const float*)d_in[7];
    const float* br   = (const float*)d_in[8];
    const float* We   = (const float*)d_in[9];
    const float* att  = (const float*)d_in[10];
    const float* gb   = (const float*)d_in[11];
    const float* lng  = (const float*)d_in[12];
    const float* lnb  = (const float*)d_in[13];
    const float* p1W  = (const float*)d_in[14];
    const float* p1b  = (const float*)d_in[15];
    const float* p2W  = (const float*)d_in[16];
    const float* p2b  = (const float*)d_in[17];
    const float* p3W  = (const float*)d_in[18];
    const float* p3b  = (const float*)d_in[19];
    const float* v1W  = (const float*)d_in[20];
    const float* v1b  = (const float*)d_in[21];
    const float* v2W  = (const float*)d_in[22];
    const float* v2b  = (const float*)d_in[23];
    const float* coup = (const float*)d_in[24];

    int N = in_sizes[0];
    int E = in_sizes[1] / 2;
    long long P = (long long)N * (N - 1) / 2;
    float* out = (float*)d_out;

    dim3 nl((N + 7) / 8, 2);
    // order chosen so the profiler's fixed capture slot (4th launch) lands on
    // k_nodelin (k_nodelin only depends on k_emb; scan/scatter only on stats)
    k_emb<<<N, 256>>>(x, embW, embB);
    k_init<<<(N + 255) / 256, 256>>>(N);
    k_edge_stats<<<(E + 255) / 256, 256>>>(ei, ea, E);
    k_nodelin<<<nl, 128>>>(Wl, bl, Wr, br, 0, N);
    k_scan<<<1, 1024>>>(N);
    k_scatter<<<(E + 255) / 256, 256>>>(ei, ea, E);
    k_gat<<<N, 256>>>(We, att, gb, lng, lnb, 0);
    for (int l = 1; l < 4; l++) {
        k_nodelin<<<nl, 128>>>(Wl, bl, Wr, br, l, N);
        k_gat<<<N, 256>>>(We, att, gb, lng, lnb, l);
    }
    k_graph<<<1, 512>>>(v1W, v1b, v2W, v2b, coup, out, N, P);
    k_AB<<<nl, 128>>>(p1W, p1b, N);
    int pblocks = (int)((P + 127) / 128);
    k_pairs<<<pblocks, 256>>>(p2W, p2b, p3W, p3b, out, N, P);
}